// round 13
// baseline (speedup 1.0000x reference)
#include <cuda_runtime.h>

#define N_STRUCT_MAX 16384

__device__ __align__(16) float g_cinv[N_STRUCT_MAX * 12];
__device__ __align__(16) float g_cvec[N_STRUCT_MAX * 32];

// W1 [0,144): [k][p] pair (w2a[2p][k], w2a[2p+1][k])  k<9,  p<16
// W2 [144,400): [k][q] pair (w2b[2q][k], w2b[2q+1][k]) k<32, q<8
// W3 [400,448): [k][q] pair (w2c[2q][k], w2c[2q+1][k]) k<16, q<3
// B2 [448,456), B3 [456,459)
// F: w0[9] w1[9] w1n[9] b0[3] b1[3] b1n[3] (+pad)
struct ConstBlob {
    unsigned long long W[459];
    float F[40];
};

__device__ ConstBlob g_stage;     // staged by precompute kernel
__constant__ ConstBlob c_blob;    // single D2D memcpy from g_stage

#define W1C(k,p) c_blob.W[(k)*16+(p)]
#define W2C(k,q) c_blob.W[144+(k)*8+(q)]
#define W3C(k,q) c_blob.W[400+(k)*3+(q)]
#define B2C(q)   c_blob.W[448+(q)]
#define B3C(q)   c_blob.W[456+(q)]
#define CF(i)    c_blob.F[(i)]

__device__ __forceinline__ float leaky(float x) { return fmaxf(x, 0.01f * x); }

__device__ __forceinline__ unsigned long long pack2(float lo, float hi) {
    unsigned long long r;
    asm("mov.b64 %0, {%1, %2};" : "=l"(r) : "f"(lo), "f"(hi));
    return r;
}
__device__ __forceinline__ void unpack2(unsigned long long v, float& lo, float& hi) {
    asm("mov.b64 {%0, %1}, %2;" : "=f"(lo), "=f"(hi) : "l"(v));
}
__device__ __forceinline__ unsigned long long fma2(unsigned long long a, unsigned long long b,
                                                   unsigned long long c) {
    unsigned long long d;
    asm("fma.rn.f32x2 %0, %1, %2, %3;" : "=l"(d) : "l"(a), "l"(b), "l"(c));
    return d;
}

// 16 warps/block, one structure per warp; block 0 also stages transposed weights.
__global__ __launch_bounds__(512) void precompute_kernel(
    const float* __restrict__ cell,
    const float* __restrict__ w2a,
    const float* __restrict__ b2a,
    const float* __restrict__ w0, const float* __restrict__ b0,
    const float* __restrict__ w1, const float* __restrict__ b1,
    const float* __restrict__ w1n, const float* __restrict__ b1n,
    const float* __restrict__ w2b, const float* __restrict__ b2b,
    const float* __restrict__ w2c, const float* __restrict__ b2c,
    float* __restrict__ out, int S)
{
    __shared__ float sW[81 * 32];  // [t][j] = w2a[j*90+9+t]
    int tid = threadIdx.x;
    for (int i = tid; i < 81 * 32; i += blockDim.x) {
        int t = i >> 5, j = i & 31;
        sW[i] = w2a[j * 90 + 9 + t];
    }
    __syncthreads();

    if (blockIdx.x == 0) {
        for (int i = tid; i < 144; i += blockDim.x) {
            int k = i >> 4, p = i & 15;
            g_stage.W[i] = pack2(w2a[(2*p) * 90 + k], w2a[(2*p+1) * 90 + k]);
        }
        for (int i = tid; i < 256; i += blockDim.x) {
            int k = i >> 3, q = i & 7;
            g_stage.W[144 + i] = pack2(w2b[(2*q) * 32 + k], w2b[(2*q+1) * 32 + k]);
        }
        for (int i = tid; i < 48; i += blockDim.x) {
            int k = i / 3, q = i - 3 * k;
            g_stage.W[400 + i] = pack2(w2c[(2*q) * 16 + k], w2c[(2*q+1) * 16 + k]);
        }
        if (tid < 8) g_stage.W[448 + tid] = pack2(b2b[2*tid], b2b[2*tid+1]);
        else if (tid < 11) { int q = tid - 8; g_stage.W[456 + q] = pack2(b2c[2*q], b2c[2*q+1]); }
        else if (tid >= 32 && tid < 72) {
            int t = tid - 32;
            float v = 0.f;
            if (t < 9)       v = w0[t];
            else if (t < 18) v = w1[t - 9];
            else if (t < 27) v = w1n[t - 18];
            else if (t < 30) v = b0[t - 27];
            else if (t < 33) v = b1[t - 30];
            else if (t < 36) v = b1n[t - 33];
            g_stage.F[t] = v;
        }
    }

    int warpId = tid >> 5;
    int lane = tid & 31;
    int s = blockIdx.x * 16 + warpId;
    if (s >= S) return;

    float m[9];
#pragma unroll
    for (int i = 0; i < 9; i++) m[i] = __ldg(cell + s * 9 + i);

    float acc = b2a[lane];
#pragma unroll
    for (int p = 0; p < 9; p++) {
        float mp = m[p];
#pragma unroll
        for (int q = 0; q < 9; q++)
            acc = fmaf(sW[(p * 9 + q) * 32 + lane], mp * m[q], acc);
    }
    g_cvec[s * 32 + lane] = acc;

    if (lane < 6) out[s * 6 + lane] = 0.f;

    if (lane == 0) {
        float c00 = m[4] * m[8] - m[5] * m[7];
        float c01 = m[5] * m[6] - m[3] * m[8];
        float c02 = m[3] * m[7] - m[4] * m[6];
        float det = m[0] * c00 + m[1] * c01 + m[2] * c02;
        float id = 1.f / det;
        float4* o = (float4*)(g_cinv + s * 12);
        float4 r0, r1, r2;
        r0.x = c00 * id;
        r0.y = (m[2] * m[7] - m[1] * m[8]) * id;
        r0.z = (m[1] * m[5] - m[2] * m[4]) * id;
        r0.w = c01 * id;
        r1.x = (m[0] * m[8] - m[2] * m[6]) * id;
        r1.y = (m[2] * m[3] - m[0] * m[5]) * id;
        r1.z = c02 * id;
        r1.w = (m[1] * m[6] - m[0] * m[7]) * id;
        r2.x = (m[0] * m[4] - m[1] * m[3]) * id;
        r2.y = 0.f; r2.z = 0.f; r2.w = 0.f;
        o[0] = r0; o[1] = r1; o[2] = r2;
    }
}

// 2 atoms per thread; weights in __constant__ (uniform port); pre-packed x.
__global__ void __launch_bounds__(128, 6) atom_kernel(
    const float* __restrict__ atom_prop, const float* __restrict__ pos,
    const int* __restrict__ batch,
    float* __restrict__ out, int n)
{
    int tid = threadIdx.x;
    int lane = tid & 31;
    int i0 = (blockIdx.x * blockDim.x + tid) * 2;
    int i1 = i0 + 1;
    bool v0 = i0 < n, v1 = i1 < n;
    int b0i, b1i;
    if (v1) {
        int2 bb = *(const int2*)(batch + i0);
        b0i = bb.x; b1i = bb.y;
    } else if (v0) {
        b0i = batch[i0]; b1i = b0i;
    } else {
        b0i = -1; b1i = -1;
    }

    float hA[6], hB[6];
#pragma unroll
    for (int k = 0; k < 6; k++) { hA[k] = 0.f; hB[k] = 0.f; }

    if (v0) {
        // ---- head ----
        const float2* pp = (const float2*)(pos + 3 * i0);
        float2 q0 = pp[0], q1 = pp[1], q2 = v1 ? pp[2] : make_float2(0.f, 0.f);
        const float2* ap = (const float2*)(atom_prop + 3 * i0);
        float2 a0 = ap[0], a1 = ap[1], a2 = v1 ? ap[2] : make_float2(0.f, 0.f);

        float pA[3] = {q0.x, q0.y, q1.x};
        float pB[3] = {q1.y, q2.x, q2.y};
        float apA[3] = {a0.x, a0.y, a1.x};
        float apB[3] = {a1.y, a2.x, a2.y};

        // packed per-atom feature vectors (each u64 holds (x,x) broadcast pair)
        unsigned long long xdA[9], xdB[9];
#pragma unroll
        for (int at = 0; at < 2; at++) {
            int bb = at ? b1i : b0i;
            const float* P = at ? pB : pA;
            const float* AP = at ? apB : apA;
            unsigned long long* XD = at ? xdB : xdA;
            const float4* civ = (const float4*)(g_cinv + bb * 12);
            float4 c0 = civ[0], c1 = civ[1], c2 = civ[2];
            float ci[9] = {c0.x, c0.y, c0.z, c0.w, c1.x, c1.y, c1.z, c1.w, c2.x};
            float th[3];
#pragma unroll
            for (int e = 0; e < 3; e++) {
                float f = fmaf(P[0], ci[e], fmaf(P[1], ci[3 + e], P[2] * ci[6 + e]));
                th[e] = f - floorf(f) - 0.5f;
            }
            XD[0] = pack2(AP[0], AP[0]);
            XD[1] = pack2(AP[1], AP[1]);
            XD[2] = pack2(AP[2], AP[2]);
#pragma unroll
            for (int j = 0; j < 3; j++) {
                float a = leaky(fmaf(CF(j*3), AP[0], fmaf(CF(j*3+1), AP[1], fmaf(CF(j*3+2), AP[2], CF(27+j)))));
                float u = fmaf(CF(9+j*3), th[0], fmaf(CF(9+j*3+1), th[1], fmaf(CF(9+j*3+2), th[2], CF(30+j))));
                float v = CF(33+j) - fmaf(CF(18+j*3), th[0], fmaf(CF(18+j*3+1), th[1], CF(18+j*3+2) * th[2]));
                float t1 = fmaxf(u, 0.f) * a;
                float t2 = fmaxf(v, 0.f) * a;
                XD[3 + j] = pack2(t1, t1);
                XD[6 + j] = pack2(t2, t2);
            }
        }

        // ---- layer-2 accumulators ----
        unsigned long long acc2A[8], acc2B[8];
#pragma unroll
        for (int q = 0; q < 8; q++) {
            unsigned long long bb = B2C(q);
            acc2A[q] = bb; acc2B[q] = bb;
        }

        // ---- layer 1: four 8-output tiles, fused into layer 2 ----
#pragma unroll
        for (int jt = 0; jt < 4; jt++) {
            unsigned long long a1A[4], a1B[4];
            const float4* cvA = (const float4*)(g_cvec + b0i * 32) + jt * 2;
            const float4* cvB = (const float4*)(g_cvec + b1i * 32) + jt * 2;
#pragma unroll
            for (int q = 0; q < 2; q++) {
                float4 ca = cvA[q], cb = cvB[q];
                a1A[2*q]   = pack2(ca.x, ca.y);
                a1A[2*q+1] = pack2(ca.z, ca.w);
                a1B[2*q]   = pack2(cb.x, cb.y);
                a1B[2*q+1] = pack2(cb.z, cb.w);
            }
#pragma unroll
            for (int k = 0; k < 9; k++) {
#pragma unroll
                for (int q = 0; q < 4; q++) {
                    unsigned long long w = W1C(k, jt * 4 + q);
                    a1A[q] = fma2(w, xdA[k], a1A[q]);
                    a1B[q] = fma2(w, xdB[k], a1B[q]);
                }
            }
            // fuse: relu(h1) -> layer 2
#pragma unroll
            for (int p = 0; p < 4; p++) {
                float lA0, lA1, lB0, lB1;
                unpack2(a1A[p], lA0, lA1);
                unpack2(a1B[p], lB0, lB1);
                lA0 = fmaxf(lA0, 0.f); lA1 = fmaxf(lA1, 0.f);
                lB0 = fmaxf(lB0, 0.f); lB1 = fmaxf(lB1, 0.f);
#pragma unroll
                for (int r = 0; r < 2; r++) {
                    int k2i = jt * 8 + 2 * p + r;
                    unsigned long long xa = pack2(r ? lA1 : lA0, r ? lA1 : lA0);
                    unsigned long long xb = pack2(r ? lB1 : lB0, r ? lB1 : lB0);
#pragma unroll
                    for (int q = 0; q < 8; q++) {
                        unsigned long long w = W2C(k2i, q);
                        acc2A[q] = fma2(w, xa, acc2A[q]);
                        acc2B[q] = fma2(w, xb, acc2B[q]);
                    }
                }
            }
        }

        // ---- layer 3 fused from acc2 (6 outputs: 3 u64 accs) ----
        unsigned long long acc3A[3], acc3B[3];
#pragma unroll
        for (int q = 0; q < 3; q++) {
            unsigned long long bb = B3C(q);
            acc3A[q] = bb; acc3B[q] = bb;
        }
#pragma unroll
        for (int p = 0; p < 8; p++) {
            float lA0, lA1, lB0, lB1;
            unpack2(acc2A[p], lA0, lA1);
            unpack2(acc2B[p], lB0, lB1);
            lA0 = leaky(lA0); lA1 = leaky(lA1);
            lB0 = leaky(lB0); lB1 = leaky(lB1);
#pragma unroll
            for (int r = 0; r < 2; r++) {
                int k3i = 2 * p + r;
                unsigned long long xa = pack2(r ? lA1 : lA0, r ? lA1 : lA0);
                unsigned long long xb = pack2(r ? lB1 : lB0, r ? lB1 : lB0);
#pragma unroll
                for (int q = 0; q < 3; q++) {
                    unsigned long long w = W3C(k3i, q);
                    acc3A[q] = fma2(w, xa, acc3A[q]);
                    acc3B[q] = fma2(w, xb, acc3B[q]);
                }
            }
        }
#pragma unroll
        for (int p = 0; p < 3; p++) {
            unpack2(acc3A[p], hA[2*p], hA[2*p+1]);
            unpack2(acc3B[p], hB[2*p], hB[2*p+1]);
        }
        if (!v1) {
#pragma unroll
            for (int k = 0; k < 6; k++) hB[k] = 0.f;
        }
    }

    // ---- segmented reduction over sorted batch (2 atoms/thread) ----
    float vscan[6];
    bool split = (b0i != b1i);
#pragma unroll
    for (int k = 0; k < 6; k++) vscan[k] = split ? hB[k] : (hA[k] + hB[k]);

    const unsigned mask = 0xffffffffu;
    unsigned mseg = __match_any_sync(mask, b1i);
    int head = __ffs(mseg) - 1;
#pragma unroll
    for (int d = 1; d < 32; d <<= 1) {
        bool take = (lane >= head + d);
#pragma unroll
        for (int k = 0; k < 6; k++) {
            float o = __shfl_up_sync(mask, vscan[k], d);
            if (take) vscan[k] += o;
        }
    }

    int bprev = __shfl_up_sync(mask, b1i, 1);
    float sprev[6];
#pragma unroll
    for (int k = 0; k < 6; k++) sprev[k] = __shfl_up_sync(mask, vscan[k], 1);
    int bnext0 = __shfl_down_sync(mask, b0i, 1);

    if (split && b0i >= 0) {
        bool carry = (lane > 0) && (bprev == b0i);
#pragma unroll
        for (int k = 0; k < 6; k++) {
            float t = hA[k] + (carry ? sprev[k] : 0.f);
            atomicAdd(&out[b0i * 6 + k], t);
        }
    }
    bool tail = (lane == 31) || (bnext0 != b1i);
    if (b1i >= 0 && tail) {
#pragma unroll
        for (int k = 0; k < 6; k++) atomicAdd(&out[b1i * 6 + k], vscan[k]);
    }
}

extern "C" void kernel_launch(void* const* d_in, const int* in_sizes, int n_in,
                              void* d_out, int out_size)
{
    const float* atom_prop = (const float*)d_in[0];
    const float* pos       = (const float*)d_in[1];
    const float* cell      = (const float*)d_in[2];
    const int*   batch     = (const int*)d_in[3];
    const float* w0  = (const float*)d_in[4];
    const float* b0  = (const float*)d_in[5];
    const float* w1  = (const float*)d_in[6];
    const float* b1  = (const float*)d_in[7];
    const float* w1n = (const float*)d_in[8];
    const float* b1n = (const float*)d_in[9];
    const float* w2a = (const float*)d_in[10];
    const float* b2a = (const float*)d_in[11];
    const float* w2b = (const float*)d_in[12];
    const float* b2b = (const float*)d_in[13];
    const float* w2c = (const float*)d_in[14];
    const float* b2c = (const float*)d_in[15];
    float* out = (float*)d_out;

    int n = in_sizes[3];        // N_ATOMS
    int S = in_sizes[2] / 9;    // N_STRUCT

    void *dC = nullptr, *sC = nullptr;
    cudaGetSymbolAddress(&dC, c_blob);
    cudaGetSymbolAddress(&sC, g_stage);

    precompute_kernel<<<(S + 15) / 16, 512>>>(cell, w2a, b2a,
                                              w0, b0, w1, b1, w1n, b1n,
                                              w2b, b2b, w2c, b2c, out, S);
    cudaMemcpyAsync(dC, sC, sizeof(ConstBlob), cudaMemcpyDeviceToDevice, 0);
    atom_kernel<<<(n + 255) / 256, 128>>>(atom_prop, pos, batch, out, n);
}

// round 14
// speedup vs baseline: 1.7724x; 1.7724x over previous
#include <cuda_runtime.h>

#define N_STRUCT_MAX 16384

__device__ __align__(16) float g_cinv[N_STRUCT_MAX * 12];
__device__ __align__(16) float g_cvec[N_STRUCT_MAX * 32];

// W1 [0,144): [k][p] pair (w2a[2p][k], w2a[2p+1][k])  k<9,  p<16
// W2 [144,400): [k][q] pair (w2b[2q][k], w2b[2q+1][k]) k<32, q<8
// W3 [400,448): [k][q] pair (w2c[2q][k], w2c[2q+1][k]) k<16, q<3
// B2 [448,456), B3 [456,459)
// F: w0[9] w1[9] w1n[9] b0[3] b1[3] b1n[3] (+pad)
struct ConstBlob {
    unsigned long long W[459];
    float F[40];
};

__device__ ConstBlob g_stage;     // staged by precompute kernel
__constant__ ConstBlob c_blob;    // single D2D memcpy from g_stage

#define W1C(k,p) c_blob.W[(k)*16+(p)]
#define W2C(k,q) c_blob.W[144+(k)*8+(q)]
#define W3C(k,q) c_blob.W[400+(k)*3+(q)]
#define B2C(q)   c_blob.W[448+(q)]
#define B3C(q)   c_blob.W[456+(q)]
#define CF(i)    c_blob.F[(i)]

__device__ __forceinline__ float leaky(float x) { return fmaxf(x, 0.01f * x); }

__device__ __forceinline__ unsigned long long pack2(float lo, float hi) {
    unsigned long long r;
    asm("mov.b64 %0, {%1, %2};" : "=l"(r) : "f"(lo), "f"(hi));
    return r;
}
__device__ __forceinline__ void unpack2(unsigned long long v, float& lo, float& hi) {
    asm("mov.b64 {%0, %1}, %2;" : "=f"(lo), "=f"(hi) : "l"(v));
}
__device__ __forceinline__ unsigned long long fma2(unsigned long long a, unsigned long long b,
                                                   unsigned long long c) {
    unsigned long long d;
    asm("fma.rn.f32x2 %0, %1, %2, %3;" : "=l"(d) : "l"(a), "l"(b), "l"(c));
    return d;
}

// 16 warps/block, one structure per warp; block 0 also stages transposed weights.
__global__ __launch_bounds__(512) void precompute_kernel(
    const float* __restrict__ cell,
    const float* __restrict__ w2a,
    const float* __restrict__ b2a,
    const float* __restrict__ w0, const float* __restrict__ b0,
    const float* __restrict__ w1, const float* __restrict__ b1,
    const float* __restrict__ w1n, const float* __restrict__ b1n,
    const float* __restrict__ w2b, const float* __restrict__ b2b,
    const float* __restrict__ w2c, const float* __restrict__ b2c,
    float* __restrict__ out, int S)
{
    __shared__ float sW[81 * 32];  // [t][j] = w2a[j*90+9+t]
    int tid = threadIdx.x;
    for (int i = tid; i < 81 * 32; i += blockDim.x) {
        int t = i >> 5, j = i & 31;
        sW[i] = w2a[j * 90 + 9 + t];
    }
    __syncthreads();

    if (blockIdx.x == 0) {
        for (int i = tid; i < 144; i += blockDim.x) {
            int k = i >> 4, p = i & 15;
            g_stage.W[i] = pack2(w2a[(2*p) * 90 + k], w2a[(2*p+1) * 90 + k]);
        }
        for (int i = tid; i < 256; i += blockDim.x) {
            int k = i >> 3, q = i & 7;
            g_stage.W[144 + i] = pack2(w2b[(2*q) * 32 + k], w2b[(2*q+1) * 32 + k]);
        }
        for (int i = tid; i < 48; i += blockDim.x) {
            int k = i / 3, q = i - 3 * k;
            g_stage.W[400 + i] = pack2(w2c[(2*q) * 16 + k], w2c[(2*q+1) * 16 + k]);
        }
        if (tid < 8) g_stage.W[448 + tid] = pack2(b2b[2*tid], b2b[2*tid+1]);
        else if (tid < 11) { int q = tid - 8; g_stage.W[456 + q] = pack2(b2c[2*q], b2c[2*q+1]); }
        else if (tid >= 32 && tid < 72) {
            int t = tid - 32;
            float v = 0.f;
            if (t < 9)       v = w0[t];
            else if (t < 18) v = w1[t - 9];
            else if (t < 27) v = w1n[t - 18];
            else if (t < 30) v = b0[t - 27];
            else if (t < 33) v = b1[t - 30];
            else if (t < 36) v = b1n[t - 33];
            g_stage.F[t] = v;
        }
    }

    int warpId = tid >> 5;
    int lane = tid & 31;
    int s = blockIdx.x * 16 + warpId;
    if (s >= S) return;

    float m[9];
#pragma unroll
    for (int i = 0; i < 9; i++) m[i] = __ldg(cell + s * 9 + i);

    float acc = b2a[lane];
#pragma unroll
    for (int p = 0; p < 9; p++) {
        float mp = m[p];
#pragma unroll
        for (int q = 0; q < 9; q++)
            acc = fmaf(sW[(p * 9 + q) * 32 + lane], mp * m[q], acc);
    }
    g_cvec[s * 32 + lane] = acc;

    if (lane < 6) out[s * 6 + lane] = 0.f;

    if (lane == 0) {
        float c00 = m[4] * m[8] - m[5] * m[7];
        float c01 = m[5] * m[6] - m[3] * m[8];
        float c02 = m[3] * m[7] - m[4] * m[6];
        float det = m[0] * c00 + m[1] * c01 + m[2] * c02;
        float id = 1.f / det;
        float4* o = (float4*)(g_cinv + s * 12);
        float4 r0, r1, r2;
        r0.x = c00 * id;
        r0.y = (m[2] * m[7] - m[1] * m[8]) * id;
        r0.z = (m[1] * m[5] - m[2] * m[4]) * id;
        r0.w = c01 * id;
        r1.x = (m[0] * m[8] - m[2] * m[6]) * id;
        r1.y = (m[2] * m[3] - m[0] * m[5]) * id;
        r1.z = c02 * id;
        r1.w = (m[1] * m[6] - m[0] * m[7]) * id;
        r2.x = (m[0] * m[4] - m[1] * m[3]) * id;
        r2.y = 0.f; r2.z = 0.f; r2.w = 0.f;
        o[0] = r0; o[1] = r1; o[2] = r2;
    }
}

// 2 atoms per thread; weights in __constant__ (uniform port); pre-packed x.
// (128,5): regs settle at ~88 — measured optimum; (128,6) spills (round 13).
__global__ void __launch_bounds__(128, 5) atom_kernel(
    const float* __restrict__ atom_prop, const float* __restrict__ pos,
    const int* __restrict__ batch,
    float* __restrict__ out, int n)
{
    int tid = threadIdx.x;
    int lane = tid & 31;
    int i0 = (blockIdx.x * blockDim.x + tid) * 2;
    int i1 = i0 + 1;
    bool v0 = i0 < n, v1 = i1 < n;
    int b0i, b1i;
    if (v1) {
        int2 bb = *(const int2*)(batch + i0);
        b0i = bb.x; b1i = bb.y;
    } else if (v0) {
        b0i = batch[i0]; b1i = b0i;
    } else {
        b0i = -1; b1i = -1;
    }

    float hA[6], hB[6];
#pragma unroll
    for (int k = 0; k < 6; k++) { hA[k] = 0.f; hB[k] = 0.f; }

    if (v0) {
        // ---- head ----
        const float2* pp = (const float2*)(pos + 3 * i0);
        float2 q0 = pp[0], q1 = pp[1], q2 = v1 ? pp[2] : make_float2(0.f, 0.f);
        const float2* ap = (const float2*)(atom_prop + 3 * i0);
        float2 a0 = ap[0], a1 = ap[1], a2 = v1 ? ap[2] : make_float2(0.f, 0.f);

        float pA[3] = {q0.x, q0.y, q1.x};
        float pB[3] = {q1.y, q2.x, q2.y};
        float apA[3] = {a0.x, a0.y, a1.x};
        float apB[3] = {a1.y, a2.x, a2.y};

        // packed per-atom feature vectors (each u64 holds (x,x) broadcast pair)
        unsigned long long xdA[9], xdB[9];
#pragma unroll
        for (int at = 0; at < 2; at++) {
            int bb = at ? b1i : b0i;
            const float* P = at ? pB : pA;
            const float* AP = at ? apB : apA;
            unsigned long long* XD = at ? xdB : xdA;
            const float4* civ = (const float4*)(g_cinv + bb * 12);
            float4 c0 = civ[0], c1 = civ[1], c2 = civ[2];
            float ci[9] = {c0.x, c0.y, c0.z, c0.w, c1.x, c1.y, c1.z, c1.w, c2.x};
            float th[3];
#pragma unroll
            for (int e = 0; e < 3; e++) {
                float f = fmaf(P[0], ci[e], fmaf(P[1], ci[3 + e], P[2] * ci[6 + e]));
                th[e] = f - floorf(f) - 0.5f;
            }
            XD[0] = pack2(AP[0], AP[0]);
            XD[1] = pack2(AP[1], AP[1]);
            XD[2] = pack2(AP[2], AP[2]);
#pragma unroll
            for (int j = 0; j < 3; j++) {
                float a = leaky(fmaf(CF(j*3), AP[0], fmaf(CF(j*3+1), AP[1], fmaf(CF(j*3+2), AP[2], CF(27+j)))));
                float u = fmaf(CF(9+j*3), th[0], fmaf(CF(9+j*3+1), th[1], fmaf(CF(9+j*3+2), th[2], CF(30+j))));
                float v = CF(33+j) - fmaf(CF(18+j*3), th[0], fmaf(CF(18+j*3+1), th[1], CF(18+j*3+2) * th[2]));
                float t1 = fmaxf(u, 0.f) * a;
                float t2 = fmaxf(v, 0.f) * a;
                XD[3 + j] = pack2(t1, t1);
                XD[6 + j] = pack2(t2, t2);
            }
        }

        // ---- layer-2 accumulators ----
        unsigned long long acc2A[8], acc2B[8];
#pragma unroll
        for (int q = 0; q < 8; q++) {
            unsigned long long bb = B2C(q);
            acc2A[q] = bb; acc2B[q] = bb;
        }

        // ---- layer 1: four 8-output tiles, fused into layer 2 ----
#pragma unroll
        for (int jt = 0; jt < 4; jt++) {
            unsigned long long a1A[4], a1B[4];
            const float4* cvA = (const float4*)(g_cvec + b0i * 32) + jt * 2;
            const float4* cvB = (const float4*)(g_cvec + b1i * 32) + jt * 2;
#pragma unroll
            for (int q = 0; q < 2; q++) {
                float4 ca = cvA[q], cb = cvB[q];
                a1A[2*q]   = pack2(ca.x, ca.y);
                a1A[2*q+1] = pack2(ca.z, ca.w);
                a1B[2*q]   = pack2(cb.x, cb.y);
                a1B[2*q+1] = pack2(cb.z, cb.w);
            }
#pragma unroll
            for (int k = 0; k < 9; k++) {
#pragma unroll
                for (int q = 0; q < 4; q++) {
                    unsigned long long w = W1C(k, jt * 4 + q);
                    a1A[q] = fma2(w, xdA[k], a1A[q]);
                    a1B[q] = fma2(w, xdB[k], a1B[q]);
                }
            }
            // fuse: relu(h1) -> layer 2
#pragma unroll
            for (int p = 0; p < 4; p++) {
                float lA0, lA1, lB0, lB1;
                unpack2(a1A[p], lA0, lA1);
                unpack2(a1B[p], lB0, lB1);
                lA0 = fmaxf(lA0, 0.f); lA1 = fmaxf(lA1, 0.f);
                lB0 = fmaxf(lB0, 0.f); lB1 = fmaxf(lB1, 0.f);
#pragma unroll
                for (int r = 0; r < 2; r++) {
                    int k2i = jt * 8 + 2 * p + r;
                    unsigned long long xa = pack2(r ? lA1 : lA0, r ? lA1 : lA0);
                    unsigned long long xb = pack2(r ? lB1 : lB0, r ? lB1 : lB0);
#pragma unroll
                    for (int q = 0; q < 8; q++) {
                        unsigned long long w = W2C(k2i, q);
                        acc2A[q] = fma2(w, xa, acc2A[q]);
                        acc2B[q] = fma2(w, xb, acc2B[q]);
                    }
                }
            }
        }

        // ---- layer 3 fused from acc2 (6 outputs: 3 u64 accs) ----
        unsigned long long acc3A[3], acc3B[3];
#pragma unroll
        for (int q = 0; q < 3; q++) {
            unsigned long long bb = B3C(q);
            acc3A[q] = bb; acc3B[q] = bb;
        }
#pragma unroll
        for (int p = 0; p < 8; p++) {
            float lA0, lA1, lB0, lB1;
            unpack2(acc2A[p], lA0, lA1);
            unpack2(acc2B[p], lB0, lB1);
            lA0 = leaky(lA0); lA1 = leaky(lA1);
            lB0 = leaky(lB0); lB1 = leaky(lB1);
#pragma unroll
            for (int r = 0; r < 2; r++) {
                int k3i = 2 * p + r;
                unsigned long long xa = pack2(r ? lA1 : lA0, r ? lA1 : lA0);
                unsigned long long xb = pack2(r ? lB1 : lB0, r ? lB1 : lB0);
#pragma unroll
                for (int q = 0; q < 3; q++) {
                    unsigned long long w = W3C(k3i, q);
                    acc3A[q] = fma2(w, xa, acc3A[q]);
                    acc3B[q] = fma2(w, xb, acc3B[q]);
                }
            }
        }
#pragma unroll
        for (int p = 0; p < 3; p++) {
            unpack2(acc3A[p], hA[2*p], hA[2*p+1]);
            unpack2(acc3B[p], hB[2*p], hB[2*p+1]);
        }
        if (!v1) {
#pragma unroll
            for (int k = 0; k < 6; k++) hB[k] = 0.f;
        }
    }

    // ---- segmented reduction over sorted batch (2 atoms/thread) ----
    float vscan[6];
    bool split = (b0i != b1i);
#pragma unroll
    for (int k = 0; k < 6; k++) vscan[k] = split ? hB[k] : (hA[k] + hB[k]);

    const unsigned mask = 0xffffffffu;
    unsigned mseg = __match_any_sync(mask, b1i);
    int head = __ffs(mseg) - 1;
#pragma unroll
    for (int d = 1; d < 32; d <<= 1) {
        bool take = (lane >= head + d);
#pragma unroll
        for (int k = 0; k < 6; k++) {
            float o = __shfl_up_sync(mask, vscan[k], d);
            if (take) vscan[k] += o;
        }
    }

    int bprev = __shfl_up_sync(mask, b1i, 1);
    float sprev[6];
#pragma unroll
    for (int k = 0; k < 6; k++) sprev[k] = __shfl_up_sync(mask, vscan[k], 1);
    int bnext0 = __shfl_down_sync(mask, b0i, 1);

    if (split && b0i >= 0) {
        bool carry = (lane > 0) && (bprev == b0i);
#pragma unroll
        for (int k = 0; k < 6; k++) {
            float t = hA[k] + (carry ? sprev[k] : 0.f);
            atomicAdd(&out[b0i * 6 + k], t);
        }
    }
    bool tail = (lane == 31) || (bnext0 != b1i);
    if (b1i >= 0 && tail) {
#pragma unroll
        for (int k = 0; k < 6; k++) atomicAdd(&out[b1i * 6 + k], vscan[k]);
    }
}

extern "C" void kernel_launch(void* const* d_in, const int* in_sizes, int n_in,
                              void* d_out, int out_size)
{
    const float* atom_prop = (const float*)d_in[0];
    const float* pos       = (const float*)d_in[1];
    const float* cell      = (const float*)d_in[2];
    const int*   batch     = (const int*)d_in[3];
    const float* w0  = (const float*)d_in[4];
    const float* b0  = (const float*)d_in[5];
    const float* w1  = (const float*)d_in[6];
    const float* b1  = (const float*)d_in[7];
    const float* w1n = (const float*)d_in[8];
    const float* b1n = (const float*)d_in[9];
    const float* w2a = (const float*)d_in[10];
    const float* b2a = (const float*)d_in[11];
    const float* w2b = (const float*)d_in[12];
    const float* b2b = (const float*)d_in[13];
    const float* w2c = (const float*)d_in[14];
    const float* b2c = (const float*)d_in[15];
    float* out = (float*)d_out;

    int n = in_sizes[3];        // N_ATOMS
    int S = in_sizes[2] / 9;    // N_STRUCT

    void *dC = nullptr, *sC = nullptr;
    cudaGetSymbolAddress(&dC, c_blob);
    cudaGetSymbolAddress(&sC, g_stage);

    precompute_kernel<<<(S + 15) / 16, 512>>>(cell, w2a, b2a,
                                              w0, b0, w1, b1, w1n, b1n,
                                              w2b, b2b, w2c, b2c, out, S);
    cudaMemcpyAsync(dC, sC, sizeof(ConstBlob), cudaMemcpyDeviceToDevice, 0);
    atom_kernel<<<(n + 255) / 256, 128>>>(atom_prop, pos, batch, out, n);
}